// round 9
// baseline (speedup 1.0000x reference)
#include <cuda_runtime.h>
#include <cstdint>
#include <math.h>

// Problem constants
#define BWIN   2048
#define SEQ    64
#define DIM    256
#define HEADS  8
#define HD     32
#define NW     64
#define KDIM   256
#define TBL    225
#define CPBH   512

// Scratch (device globals)
__device__ float g_Q[BWIN * HEADS * SEQ * HD];
__device__ float g_K[BWIN * HEADS * SEQ * HD];
__device__ float g_V[BWIN * HEADS * SEQ * HD];
__device__ float g_O[BWIN * SEQ * DIM];
__device__ float g_table[TBL * HEADS];
__device__ float g_bias[HEADS * SEQ * SEQ];
__device__ float g_bm[NW * HEADS * SEQ * SEQ];   // fused bias+mask, 8MB

// SW128 swizzle on byte offsets (128B rows)
#define SWZ(b) ((b) ^ (((b) >> 3) & 0x70))

__device__ __forceinline__ uint32_t smem_u32(const void* p) {
    uint32_t a;
    asm("{ .reg .u64 t; cvta.to.shared.u64 t, %1; cvt.u32.u64 %0, t; }"
        : "=r"(a) : "l"(p));
    return a;
}

#define CP16(dst_u32, src_ptr) \
    asm volatile("cp.async.cg.shared.global [%0], [%1], 16;" \
        :: "r"(dst_u32), "l"(src_ptr) : "memory")
#define CP_COMMIT() asm volatile("cp.async.commit_group;" ::: "memory")
#define CP_WAIT0()  asm volatile("cp.async.wait_group 0;" ::: "memory")

__device__ __forceinline__ uint32_t tf32_rna(float x) {
    uint32_t r;
    asm("cvt.rna.tf32.f32 %0, %1;" : "=r"(r) : "f"(x));
    return r;
}

__device__ __forceinline__ void hilo(float f, uint32_t& h, uint32_t& l) {
    h = tf32_rna(f);
    l = tf32_rna(f - __uint_as_float(h));
}

__device__ __forceinline__ void split4(float4 v, uint4& hi, uint4& lo) {
    hi.x = tf32_rna(v.x); lo.x = tf32_rna(v.x - __uint_as_float(hi.x));
    hi.y = tf32_rna(v.y); lo.y = tf32_rna(v.y - __uint_as_float(hi.y));
    hi.z = tf32_rna(v.z); lo.z = tf32_rna(v.z - __uint_as_float(hi.z));
    hi.w = tf32_rna(v.w); lo.w = tf32_rna(v.w - __uint_as_float(hi.w));
}

__device__ __forceinline__ void mma1688(float* c,
    uint32_t a0, uint32_t a1, uint32_t a2, uint32_t a3,
    uint32_t b0, uint32_t b1)
{
    asm volatile(
        "mma.sync.aligned.m16n8k8.row.col.f32.tf32.tf32.f32 "
        "{%0,%1,%2,%3},{%4,%5,%6,%7},{%8,%9},{%0,%1,%2,%3};"
        : "+f"(c[0]), "+f"(c[1]), "+f"(c[2]), "+f"(c[3])
        : "r"(a0), "r"(a1), "r"(a2), "r"(a3), "r"(b0), "r"(b1));
}

// ---------------------------------------------------------------------------
// Kernel 1: CPB MLP
// ---------------------------------------------------------------------------
__global__ __launch_bounds__(128) void cpb_table_kernel(
    const float* __restrict__ w1, const float* __restrict__ b1,
    const float* __restrict__ w2, const float* __restrict__ coords)
{
    int p = blockIdx.x;
    float c0 = coords[2 * p + 0];
    float c1 = coords[2 * p + 1];
    float acc[HEADS];
#pragma unroll
    for (int h = 0; h < HEADS; ++h) acc[h] = 0.f;

    for (int j = threadIdx.x; j < CPBH; j += 128) {
        float hid = fmaf(w1[2 * j], c0, fmaf(w1[2 * j + 1], c1, b1[j]));
        hid = fmaxf(hid, 0.f);
#pragma unroll
        for (int h = 0; h < HEADS; ++h)
            acc[h] = fmaf(hid, w2[h * CPBH + j], acc[h]);
    }
    int lane = threadIdx.x & 31, warp = threadIdx.x >> 5;
#pragma unroll
    for (int h = 0; h < HEADS; ++h)
#pragma unroll
        for (int off = 16; off; off >>= 1)
            acc[h] += __shfl_xor_sync(0xffffffffu, acc[h], off);

    __shared__ float red[4][HEADS];
    if (lane == 0)
#pragma unroll
        for (int h = 0; h < HEADS; ++h) red[warp][h] = acc[h];
    __syncthreads();
    if (threadIdx.x < HEADS) {
        float s = red[0][threadIdx.x] + red[1][threadIdx.x] +
                  red[2][threadIdx.x] + red[3][threadIdx.x];
        g_table[p * HEADS + threadIdx.x] = s;
    }
}

// ---------------------------------------------------------------------------
// Kernel 2: bias gather + 16*sigmoid
// ---------------------------------------------------------------------------
__global__ __launch_bounds__(256) void bias_gather_kernel(const int* __restrict__ rel_idx)
{
    int i = blockIdx.x * 256 + threadIdx.x;
    if (i >= HEADS * SEQ * SEQ) return;
    int h = i >> 12;
    int ij = i & 4095;
    float t = g_table[rel_idx[ij] * HEADS + h];
    g_bias[i] = 16.f / (1.f + expf(-t));
}

// ---------------------------------------------------------------------------
// Kernel 2b: fuse bias[h] + mask[w] -> g_bm[w][h][ij]
// ---------------------------------------------------------------------------
__global__ __launch_bounds__(256) void bm_fuse_kernel(const float* __restrict__ mask)
{
    int i = blockIdx.x * 256 + threadIdx.x;
    if (i >= NW * HEADS * SEQ * SEQ) return;
    int wh = i >> 12;
    int ij = i & 4095;
    int w = wh >> 3, h = wh & 7;
    g_bm[i] = g_bias[h * 4096 + ij] + mask[w * 4096 + ij];
}

// ---------------------------------------------------------------------------
// 3xTF32 mma.sync GEMM (R3 version: split at STS, hi/lo tiles in smem,
// single-buffered). CTA: 128x128 tile, 128 threads (4 warps, each 64x64),
// BK=32, K=256. smem: Ahi 0, Alo 16384, Bhi 32768, Blo 49152. Total 64KB.
// ---------------------------------------------------------------------------
#define GSMEM_TOTAL 65536

__global__ __launch_bounds__(128, 2) void mma_gemm(
    const float* __restrict__ A_in, const float* __restrict__ B,
    const float* __restrict__ q_bias, const float* __restrict__ v_bias,
    const float* __restrict__ pb, float* __restrict__ out, int mode)
{
    extern __shared__ char sm[];
    const float* A = (mode == 0) ? A_in : g_O;
    int tid = threadIdx.x;
    int lane = tid & 31, warp = tid >> 5;
    int m0 = blockIdx.y * 128;
    int n0 = blockIdx.x * 128;
    int wm = (warp >> 1) * 64;   // warp row offset in tile
    int wn = (warp & 1) * 64;    // warp col offset in tile

    float acc[4][8][4];
#pragma unroll
    for (int mi = 0; mi < 4; ++mi)
#pragma unroll
        for (int ni = 0; ni < 8; ++ni)
#pragma unroll
            for (int q = 0; q < 4; ++q) acc[mi][ni][q] = 0.f;

    int lrow = tid >> 3;     // 0..15
    int lc4 = tid & 7;       // 0..7 (float4 index within 32-wide k chunk)
    int g = lane >> 2;       // 0..7 row group
    int tk = lane & 3;       // 0..3 k-in-group

    for (int ko = 0; ko < KDIM; ko += 32) {
        __syncthreads();
#pragma unroll
        for (int q = 0; q < 8; ++q) {
            int r = lrow + q * 16;
            uint32_t so = SWZ((uint32_t)(r * 128 + lc4 * 16));
            float4 av = *(const float4*)(A + (size_t)(m0 + r) * KDIM + ko + lc4 * 4);
            uint4 ah, al;
            split4(av, ah, al);
            *(uint4*)(sm + so) = ah;
            *(uint4*)(sm + 16384 + so) = al;
            float4 bv = *(const float4*)(B + (size_t)(n0 + r) * KDIM + ko + lc4 * 4);
            uint4 bh, bl;
            split4(bv, bh, bl);
            *(uint4*)(sm + 32768 + so) = bh;
            *(uint4*)(sm + 49152 + so) = bl;
        }
        __syncthreads();

#pragma unroll
        for (int kk = 0; kk < 32; kk += 8) {
            uint32_t Ah[4][4], Al[4][4];
#pragma unroll
            for (int mi = 0; mi < 4; ++mi) {
                int r0 = wm + mi * 16 + g;
                int ck = kk + tk;
                uint32_t o00 = SWZ((uint32_t)(r0 * 128 + ck * 4));
                uint32_t o10 = SWZ((uint32_t)((r0 + 8) * 128 + ck * 4));
                uint32_t o01 = SWZ((uint32_t)(r0 * 128 + (ck + 4) * 4));
                uint32_t o11 = SWZ((uint32_t)((r0 + 8) * 128 + (ck + 4) * 4));
                Ah[mi][0] = *(const uint32_t*)(sm + o00);
                Ah[mi][1] = *(const uint32_t*)(sm + o10);
                Ah[mi][2] = *(const uint32_t*)(sm + o01);
                Ah[mi][3] = *(const uint32_t*)(sm + o11);
                Al[mi][0] = *(const uint32_t*)(sm + 16384 + o00);
                Al[mi][1] = *(const uint32_t*)(sm + 16384 + o10);
                Al[mi][2] = *(const uint32_t*)(sm + 16384 + o01);
                Al[mi][3] = *(const uint32_t*)(sm + 16384 + o11);
            }
#pragma unroll
            for (int ni = 0; ni < 8; ++ni) {
                int nr = wn + ni * 8 + g;
                int ck = kk + tk;
                uint32_t ob0 = SWZ((uint32_t)(nr * 128 + ck * 4));
                uint32_t ob1 = SWZ((uint32_t)(nr * 128 + (ck + 4) * 4));
                uint32_t bh0 = *(const uint32_t*)(sm + 32768 + ob0);
                uint32_t bh1 = *(const uint32_t*)(sm + 32768 + ob1);
                uint32_t bl0 = *(const uint32_t*)(sm + 49152 + ob0);
                uint32_t bl1 = *(const uint32_t*)(sm + 49152 + ob1);
#pragma unroll
                for (int mi = 0; mi < 4; ++mi) {
                    mma1688(acc[mi][ni], Ah[mi][0], Ah[mi][1], Ah[mi][2], Ah[mi][3], bh0, bh1);
                    mma1688(acc[mi][ni], Al[mi][0], Al[mi][1], Al[mi][2], Al[mi][3], bh0, bh1);
                    mma1688(acc[mi][ni], Ah[mi][0], Ah[mi][1], Ah[mi][2], Ah[mi][3], bl0, bl1);
                }
            }
        }
    }

    // Epilogue
#pragma unroll
    for (int mi = 0; mi < 4; ++mi) {
#pragma unroll
        for (int ni = 0; ni < 8; ++ni) {
            int r = m0 + wm + mi * 16 + g;        // rows r and r+8
            int c = n0 + wn + ni * 8 + 2 * tk;    // cols c, c+1
            if (mode == 0) {
                int which = c >> 8;
                int h = (c >> 5) & 7;
                int d = c & 31;
                float b0, b1;
                if (which == 0)      { b0 = q_bias[c];       b1 = q_bias[c + 1]; }
                else if (which == 2) { b0 = v_bias[c - 512]; b1 = v_bias[c - 511]; }
                else                 { b0 = 0.f; b1 = 0.f; }
                float* baseP = (which == 0) ? g_Q : (which == 1) ? g_K : g_V;
                int bw0 = r >> 6, n_0 = r & 63;
                int bw1 = (r + 8) >> 6, n_1 = (r + 8) & 63;
                float2 v0 = make_float2(acc[mi][ni][0] + b0, acc[mi][ni][1] + b1);
                float2 v1 = make_float2(acc[mi][ni][2] + b0, acc[mi][ni][3] + b1);
                *(float2*)(baseP + (size_t)((bw0 * 8 + h) * 64 + n_0) * 32 + d) = v0;
                *(float2*)(baseP + (size_t)((bw1 * 8 + h) * 64 + n_1) * 32 + d) = v1;
            } else {
                float b0 = pb[c], b1 = pb[c + 1];
                float2 v0 = make_float2(acc[mi][ni][0] + b0, acc[mi][ni][1] + b1);
                float2 v1 = make_float2(acc[mi][ni][2] + b0, acc[mi][ni][3] + b1);
                *(float2*)(out + (size_t)r * 256 + c) = v0;
                *(float2*)(out + (size_t)(r + 8) * 256 + c) = v1;
            }
        }
    }
}

// ---------------------------------------------------------------------------
// Fused attention with mma.sync (3xTF32), WITH cosine L2 normalization.
// (unchanged from R8 — passed with rel_err 4.6e-6)
// ---------------------------------------------------------------------------
#define ATT_PAIRB 27648
#define ATT_SMEM  (4 * ATT_PAIRB)

__global__ __launch_bounds__(256, 2) void attn_mma(const float* __restrict__ logit_scale)
{
    extern __shared__ char sm[];
    int tid = threadIdx.x;
    int lane = tid & 31, warp = tid >> 5;
    int b = blockIdx.x >> 1;
    int hgrp = (blockIdx.x & 1) * 4;
    int pair = warp >> 1;
    int h = hgrp + pair;
    int wp = warp & 1;           // warp index within pair
    int wrow = wp * 32;
    int g = lane >> 2, tk = lane & 3;

    char* pbse = sm + pair * ATT_PAIRB;
    float* qs = (float*)pbse;            // 64 x stride36
    float* ks = qs + 64 * 36;
    float* vs = ks + 64 * 36;
    float* Ps = (float*)pbse;            // 64 x stride68, overlays q+k

    // load q,k,v (fp32) via cp.async; 64 threads per pair
    {
        int ptid = tid & 63;
        const float* Qg = g_Q + (size_t)(b * 8 + h) * 2048;
        const float* Kg = g_K + (size_t)(b * 8 + h) * 2048;
        const float* Vg = g_V + (size_t)(b * 8 + h) * 2048;
        uint32_t qa = smem_u32(qs), ka = smem_u32(ks), va = smem_u32(vs);
#pragma unroll
        for (int i = 0; i < 8; ++i) {
            int idx = ptid + 64 * i;
            int r = idx >> 3, c4 = idx & 7;
            uint32_t do_ = (uint32_t)(r * 144 + c4 * 16);
            CP16(qa + do_, Qg + r * 32 + c4 * 4);
            CP16(ka + do_, Kg + r * 32 + c4 * 4);
            CP16(va + do_, Vg + r * 32 + c4 * 4);
        }
        CP_COMMIT();
        CP_WAIT0();
    }
    __syncthreads();

    // ---- cosine attention: L2-normalize q and k rows ----
    for (int r = wp; r < 128; r += 2) {
        float* row = (r < 64) ? (qs + r * 36) : (ks + (r - 64) * 36);
        float vv = row[lane];
        float ss = vv * vv;
#pragma unroll
        for (int off = 16; off; off >>= 1)
            ss += __shfl_xor_sync(0xffffffffu, ss, off);
        float inv = 1.f / fmaxf(sqrtf(ss), 1e-12f);
        row[lane] = vv * inv;
    }
    __syncthreads();

    float sc = __expf(fminf(logit_scale[h], 4.6051701859880913f));

    // ---- QK^T (3xTF32): warp computes rows wrow..wrow+31 x cols 0..63 ----
    float acc[2][8][4];
#pragma unroll
    for (int mi = 0; mi < 2; ++mi)
#pragma unroll
        for (int ni = 0; ni < 8; ++ni)
#pragma unroll
            for (int q = 0; q < 4; ++q) acc[mi][ni][q] = 0.f;

#pragma unroll
    for (int kk = 0; kk < 32; kk += 8) {
        uint32_t Ah[2][4], Al[2][4];
#pragma unroll
        for (int mi = 0; mi < 2; ++mi) {
            int r0 = wrow + mi * 16 + g;
            int r1 = r0 + 8;
            hilo(qs[r0 * 36 + kk + tk],     Ah[mi][0], Al[mi][0]);
            hilo(qs[r1 * 36 + kk + tk],     Ah[mi][1], Al[mi][1]);
            hilo(qs[r0 * 36 + kk + tk + 4], Ah[mi][2], Al[mi][2]);
            hilo(qs[r1 * 36 + kk + tk + 4], Ah[mi][3], Al[mi][3]);
        }
#pragma unroll
        for (int ni = 0; ni < 8; ++ni) {
            int nr = ni * 8 + g;
            uint32_t bh0, bl0, bh1, bl1;
            hilo(ks[nr * 36 + kk + tk],     bh0, bl0);
            hilo(ks[nr * 36 + kk + tk + 4], bh1, bl1);
#pragma unroll
            for (int mi = 0; mi < 2; ++mi) {
                mma1688(acc[mi][ni], Ah[mi][0], Ah[mi][1], Ah[mi][2], Ah[mi][3], bh0, bh1);
                mma1688(acc[mi][ni], Al[mi][0], Al[mi][1], Al[mi][2], Al[mi][3], bh0, bh1);
                mma1688(acc[mi][ni], Ah[mi][0], Ah[mi][1], Ah[mi][2], Ah[mi][3], bl0, bl1);
            }
        }
    }

    // ---- logits + softmax (registers + quad shuffles) ----
    const float* bm = g_bm + (size_t)(((b & (NW - 1)) * 8 + h)) * 4096;
#pragma unroll
    for (int mi = 0; mi < 2; ++mi) {
        int rA = wrow + mi * 16 + g;
        int rB = rA + 8;
        float mxA = -1e30f, mxB = -1e30f;
#pragma unroll
        for (int ni = 0; ni < 8; ++ni) {
            int c = ni * 8 + 2 * tk;
            float2 bA = *(const float2*)(bm + rA * 64 + c);
            float2 bB = *(const float2*)(bm + rB * 64 + c);
            acc[mi][ni][0] = fmaf(sc, acc[mi][ni][0], bA.x);
            acc[mi][ni][1] = fmaf(sc, acc[mi][ni][1], bA.y);
            acc[mi][ni][2] = fmaf(sc, acc[mi][ni][2], bB.x);
            acc[mi][ni][3] = fmaf(sc, acc[mi][ni][3], bB.y);
            mxA = fmaxf(mxA, fmaxf(acc[mi][ni][0], acc[mi][ni][1]));
            mxB = fmaxf(mxB, fmaxf(acc[mi][ni][2], acc[mi][ni][3]));
        }
        mxA = fmaxf(mxA, __shfl_xor_sync(0xffffffffu, mxA, 1));
        mxA = fmaxf(mxA, __shfl_xor_sync(0xffffffffu, mxA, 2));
        mxB = fmaxf(mxB, __shfl_xor_sync(0xffffffffu, mxB, 1));
        mxB = fmaxf(mxB, __shfl_xor_sync(0xffffffffu, mxB, 2));
        float sA = 0.f, sB = 0.f;
#pragma unroll
        for (int ni = 0; ni < 8; ++ni) {
            acc[mi][ni][0] = __expf(acc[mi][ni][0] - mxA);
            acc[mi][ni][1] = __expf(acc[mi][ni][1] - mxA);
            acc[mi][ni][2] = __expf(acc[mi][ni][2] - mxB);
            acc[mi][ni][3] = __expf(acc[mi][ni][3] - mxB);
            sA += acc[mi][ni][0] + acc[mi][ni][1];
            sB += acc[mi][ni][2] + acc[mi][ni][3];
        }
        sA += __shfl_xor_sync(0xffffffffu, sA, 1);
        sA += __shfl_xor_sync(0xffffffffu, sA, 2);
        sB += __shfl_xor_sync(0xffffffffu, sB, 1);
        sB += __shfl_xor_sync(0xffffffffu, sB, 2);
        float iA = 1.f / sA, iB = 1.f / sB;
#pragma unroll
        for (int ni = 0; ni < 8; ++ni) {
            acc[mi][ni][0] *= iA;
            acc[mi][ni][1] *= iA;
            acc[mi][ni][2] *= iB;
            acc[mi][ni][3] *= iB;
        }
    }

    __syncthreads();   // everyone done reading q/k before P overlays them

    // store P (fp32, stride 68)
#pragma unroll
    for (int mi = 0; mi < 2; ++mi) {
        int rA = wrow + mi * 16 + g;
        int rB = rA + 8;
#pragma unroll
        for (int ni = 0; ni < 8; ++ni) {
            int c = ni * 8 + 2 * tk;
            *(float2*)(Ps + rA * 68 + c) = make_float2(acc[mi][ni][0], acc[mi][ni][1]);
            *(float2*)(Ps + rB * 68 + c) = make_float2(acc[mi][ni][2], acc[mi][ni][3]);
        }
    }
    __syncthreads();

    // ---- AV (3xTF32): out rows wrow..+31 x dims 0..31, k over 64 tokens ----
    float o[2][4][4];
#pragma unroll
    for (int mi = 0; mi < 2; ++mi)
#pragma unroll
        for (int ni = 0; ni < 4; ++ni)
#pragma unroll
            for (int q = 0; q < 4; ++q) o[mi][ni][q] = 0.f;

#pragma unroll
    for (int kk = 0; kk < 64; kk += 8) {
        uint32_t Ph[2][4], Pl[2][4];
#pragma unroll
        for (int mi = 0; mi < 2; ++mi) {
            int r0 = wrow + mi * 16 + g;
            int r1 = r0 + 8;
            hilo(Ps[r0 * 68 + kk + tk],     Ph[mi][0], Pl[mi][0]);
            hilo(Ps[r1 * 68 + kk + tk],     Ph[mi][1], Pl[mi][1]);
            hilo(Ps[r0 * 68 + kk + tk + 4], Ph[mi][2], Pl[mi][2]);
            hilo(Ps[r1 * 68 + kk + tk + 4], Ph[mi][3], Pl[mi][3]);
        }
#pragma unroll
        for (int ni = 0; ni < 4; ++ni) {
            int d = ni * 8 + g;
            uint32_t vh0, vl0, vh1, vl1;
            hilo(vs[(kk + tk) * 36 + d],     vh0, vl0);
            hilo(vs[(kk + tk + 4) * 36 + d], vh1, vl1);
#pragma unroll
            for (int mi = 0; mi < 2; ++mi) {
                mma1688(o[mi][ni], Ph[mi][0], Ph[mi][1], Ph[mi][2], Ph[mi][3], vh0, vh1);
                mma1688(o[mi][ni], Pl[mi][0], Pl[mi][1], Pl[mi][2], Pl[mi][3], vh0, vh1);
                mma1688(o[mi][ni], Ph[mi][0], Ph[mi][1], Ph[mi][2], Ph[mi][3], vl0, vl1);
            }
        }
    }

    // write O
    float* Og = g_O + (size_t)b * 64 * 256 + h * 32;
#pragma unroll
    for (int mi = 0; mi < 2; ++mi) {
        int r0 = wrow + mi * 16 + g;
        int r1 = r0 + 8;
#pragma unroll
        for (int ni = 0; ni < 4; ++ni) {
            int c = ni * 8 + 2 * tk;
            *(float2*)(Og + (size_t)r0 * 256 + c) = make_float2(o[mi][ni][0], o[mi][ni][1]);
            *(float2*)(Og + (size_t)r1 * 256 + c) = make_float2(o[mi][ni][2], o[mi][ni][3]);
        }
    }
}

// ---------------------------------------------------------------------------
extern "C" void kernel_launch(void* const* d_in, const int* in_sizes, int n_in,
                              void* d_out, int out_size)
{
    const float* x           = (const float*)d_in[0];
    const float* mask        = (const float*)d_in[1];
    const float* qkv_w       = (const float*)d_in[2];
    const float* q_bias      = (const float*)d_in[3];
    const float* v_bias      = (const float*)d_in[4];
    const float* logit_scale = (const float*)d_in[5];
    const float* cpb_w1      = (const float*)d_in[6];
    const float* cpb_b1      = (const float*)d_in[7];
    const float* cpb_w2      = (const float*)d_in[8];
    const float* proj_w      = (const float*)d_in[9];
    const float* proj_b      = (const float*)d_in[10];
    const float* coords      = (const float*)d_in[11];
    const int*   rel_idx     = (const int*)d_in[12];
    float* out = (float*)d_out;

    static int configured = 0;
    if (!configured) {
        cudaFuncSetAttribute(mma_gemm, cudaFuncAttributeMaxDynamicSharedMemorySize,
                             GSMEM_TOTAL);
        cudaFuncSetAttribute(attn_mma, cudaFuncAttributeMaxDynamicSharedMemorySize,
                             ATT_SMEM);
        configured = 1;
    }

    cpb_table_kernel<<<TBL, 128>>>(cpb_w1, cpb_b1, cpb_w2, coords);
    bias_gather_kernel<<<(HEADS * SEQ * SEQ + 255) / 256, 256>>>(rel_idx);
    bm_fuse_kernel<<<(NW * HEADS * SEQ * SEQ + 255) / 256, 256>>>(mask);
    mma_gemm<<<dim3(6, 1024), 128, GSMEM_TOTAL>>>(x, qkv_w, q_bias, v_bias,
                                                  nullptr, nullptr, 0);
    attn_mma<<<BWIN * 2, 256, ATT_SMEM>>>(logit_scale);
    mma_gemm<<<dim3(2, 1024), 128, GSMEM_TOTAL>>>(nullptr, proj_w, nullptr, nullptr,
                                                  proj_b, out, 1);
}

// round 11
// speedup vs baseline: 1.5710x; 1.5710x over previous
#include <cuda_runtime.h>
#include <cuda_bf16.h>
#include <cstdint>
#include <math.h>

// Problem constants
#define BWIN   2048
#define SEQ    64
#define DIM    256
#define HEADS  8
#define HD     32
#define NW     64
#define KDIM   256
#define TBL    225
#define CPBH   512

// Scratch (device globals)
__device__ float g_Q[BWIN * HEADS * SEQ * HD];
__device__ float g_K[BWIN * HEADS * SEQ * HD];
__device__ float g_V[BWIN * HEADS * SEQ * HD];
__device__ float g_O[BWIN * SEQ * DIM];
__device__ float g_table[TBL * HEADS];
__device__ float g_bias[HEADS * SEQ * SEQ];

// SW128 swizzle on byte offsets (128B rows)
#define SWZ(b) ((b) ^ (((b) >> 3) & 0x70))

// bf16 2-level split of two floats, packed as k-pair words (low half = lower k)
__device__ __forceinline__ void split2_bf(float f0, float f1,
                                          uint32_t& hi, uint32_t& lo)
{
    __nv_bfloat16 h0 = __float2bfloat16_rn(f0);
    __nv_bfloat16 h1 = __float2bfloat16_rn(f1);
    float r0 = f0 - __bfloat162float(h0);
    float r1 = f1 - __bfloat162float(h1);
    __nv_bfloat16 l0 = __float2bfloat16_rn(r0);
    __nv_bfloat16 l1 = __float2bfloat16_rn(r1);
    hi = (uint32_t)__bfloat16_as_ushort(h0) | ((uint32_t)__bfloat16_as_ushort(h1) << 16);
    lo = (uint32_t)__bfloat16_as_ushort(l0) | ((uint32_t)__bfloat16_as_ushort(l1) << 16);
}

__device__ __forceinline__ void mma16816(float* c,
    uint32_t a0, uint32_t a1, uint32_t a2, uint32_t a3,
    uint32_t b0, uint32_t b1)
{
    asm volatile(
        "mma.sync.aligned.m16n8k16.row.col.f32.bf16.bf16.f32 "
        "{%0,%1,%2,%3},{%4,%5,%6,%7},{%8,%9},{%0,%1,%2,%3};"
        : "+f"(c[0]), "+f"(c[1]), "+f"(c[2]), "+f"(c[3])
        : "r"(a0), "r"(a1), "r"(a2), "r"(a3), "r"(b0), "r"(b1));
}

// ---------------------------------------------------------------------------
// Kernel 1: CPB MLP
// ---------------------------------------------------------------------------
__global__ __launch_bounds__(128) void cpb_table_kernel(
    const float* __restrict__ w1, const float* __restrict__ b1,
    const float* __restrict__ w2, const float* __restrict__ coords)
{
    int p = blockIdx.x;
    float c0 = coords[2 * p + 0];
    float c1 = coords[2 * p + 1];
    float acc[HEADS];
#pragma unroll
    for (int h = 0; h < HEADS; ++h) acc[h] = 0.f;

    for (int j = threadIdx.x; j < CPBH; j += 128) {
        float hid = fmaf(w1[2 * j], c0, fmaf(w1[2 * j + 1], c1, b1[j]));
        hid = fmaxf(hid, 0.f);
#pragma unroll
        for (int h = 0; h < HEADS; ++h)
            acc[h] = fmaf(hid, w2[h * CPBH + j], acc[h]);
    }
    int lane = threadIdx.x & 31, warp = threadIdx.x >> 5;
#pragma unroll
    for (int h = 0; h < HEADS; ++h)
#pragma unroll
        for (int off = 16; off; off >>= 1)
            acc[h] += __shfl_xor_sync(0xffffffffu, acc[h], off);

    __shared__ float red[4][HEADS];
    if (lane == 0)
#pragma unroll
        for (int h = 0; h < HEADS; ++h) red[warp][h] = acc[h];
    __syncthreads();
    if (threadIdx.x < HEADS) {
        float s = red[0][threadIdx.x] + red[1][threadIdx.x] +
                  red[2][threadIdx.x] + red[3][threadIdx.x];
        g_table[p * HEADS + threadIdx.x] = s;
    }
}

// ---------------------------------------------------------------------------
// Kernel 2: bias gather + 16*sigmoid
// ---------------------------------------------------------------------------
__global__ __launch_bounds__(256) void bias_gather_kernel(const int* __restrict__ rel_idx)
{
    int i = blockIdx.x * 256 + threadIdx.x;
    if (i >= HEADS * SEQ * SEQ) return;
    int h = i >> 12;
    int ij = i & 4095;
    float t = g_table[rel_idx[ij] * HEADS + h];
    g_bias[i] = 16.f / (1.f + expf(-t));
}

// ---------------------------------------------------------------------------
// 3-term bf16 mma.sync GEMM: D[m][c] = sum_k A[m][k]*B[c][k]
// D = Ah*Bh + Al*Bh + Ah*Bl  (bf16 2-level split, fp32 accumulate)
// CTA: 128x128 tile, 128 threads (4 warps, each 64x64), BK=32, K=256.
// smem: A tile 16KB at 0, B tile 16KB at 16384.
// Row layout (128B, SW128) per 8-k granule gp (gp = 0..3):
//   byte SWZ(gp*32 + 0)  : [hi k0-1, hi k2-3, lo k0-1, lo k2-3]   (uint4)
//   byte SWZ(gp*32 + 16) : [hi k4-5, hi k6-7, lo k4-5, lo k6-7]   (uint4)
// (k relative to granule start; every 16B sub-block swizzled from its OWN base)
// ---------------------------------------------------------------------------
#define GSMEM_TOTAL 32768

__global__ __launch_bounds__(128, 2) void mma_gemm(
    const float* __restrict__ A_in, const float* __restrict__ B,
    const float* __restrict__ q_bias, const float* __restrict__ v_bias,
    const float* __restrict__ pb, float* __restrict__ out, int mode)
{
    extern __shared__ char sm[];
    const float* A = (mode == 0) ? A_in : g_O;
    int tid = threadIdx.x;
    int lane = tid & 31, warp = tid >> 5;
    int m0 = blockIdx.y * 128;
    int n0 = blockIdx.x * 128;
    int wm = (warp >> 1) * 64;   // warp row offset in tile
    int wn = (warp & 1) * 64;    // warp col offset in tile

    float acc[4][8][4];
#pragma unroll
    for (int mi = 0; mi < 4; ++mi)
#pragma unroll
        for (int ni = 0; ni < 8; ++ni)
#pragma unroll
            for (int q = 0; q < 4; ++q) acc[mi][ni][q] = 0.f;

    int lrow = tid >> 2;     // 0..31
    int lc4 = tid & 3;       // 0..3 (8-element granule within 32-wide k chunk)
    int g = lane >> 2;       // 0..7 row group
    int tk = lane & 3;       // 0..3 k-pair in group

    for (int ko = 0; ko < KDIM; ko += 32) {
        __syncthreads();
        // stage: rows 0..127 of A and B, k = ko..ko+31, split to bf16 hi/lo
#pragma unroll
        for (int q = 0; q < 4; ++q) {
            int r = lrow + q * 32;
            uint32_t base = (uint32_t)(r * 128 + lc4 * 32);
            uint32_t so  = SWZ(base);        // first 16B sub-block
            uint32_t so2 = SWZ(base + 16u);  // second 16B sub-block (own swizzle!)
            const float4* pa = (const float4*)(A + (size_t)(m0 + r) * KDIM + ko + lc4 * 8);
            float4 v0 = pa[0], v1 = pa[1];
            uint4 hi, lo;
            split2_bf(v0.x, v0.y, hi.x, lo.x);
            split2_bf(v0.z, v0.w, hi.y, lo.y);
            split2_bf(v1.x, v1.y, hi.z, lo.z);
            split2_bf(v1.z, v1.w, hi.w, lo.w);
            *(uint4*)(sm + so)  = make_uint4(hi.x, hi.y, lo.x, lo.y);
            *(uint4*)(sm + so2) = make_uint4(hi.z, hi.w, lo.z, lo.w);
            const float4* pbp = (const float4*)(B + (size_t)(n0 + r) * KDIM + ko + lc4 * 8);
            float4 w0 = pbp[0], w1 = pbp[1];
            uint4 bhi, blo;
            split2_bf(w0.x, w0.y, bhi.x, blo.x);
            split2_bf(w0.z, w0.w, bhi.y, blo.y);
            split2_bf(w1.x, w1.y, bhi.z, blo.z);
            split2_bf(w1.z, w1.w, bhi.w, blo.w);
            *(uint4*)(sm + 16384 + so)  = make_uint4(bhi.x, bhi.y, blo.x, blo.y);
            *(uint4*)(sm + 16384 + so2) = make_uint4(bhi.z, bhi.w, blo.z, blo.w);
        }
        __syncthreads();

        // k16-step s uses granules 2s and 2s+1. Fragment word for k-pair tk:
        //   hi at SWZ(row*128 + gp*32 + (tk>>1)*16 + (tk&1)*4), lo at +8
        // (+8 touches only bits 0-3 after swizzle: safe, no bit-4 carry)
#pragma unroll
        for (int s = 0; s < 2; ++s) {
            uint32_t Ah[4][4], Al[4][4];
#pragma unroll
            for (int mi = 0; mi < 4; ++mi) {
                int r0 = wm + mi * 16 + g;
                int r1 = r0 + 8;
                uint32_t oa0 = (uint32_t)(2 * s) * 32u + ((tk >> 1) * 16u) + ((tk & 1) * 4u);
                uint32_t oa2 = oa0 + 32u;
                uint32_t b00 = SWZ((uint32_t)(r0 * 128) + oa0);
                uint32_t b10 = SWZ((uint32_t)(r1 * 128) + oa0);
                uint32_t b01 = SWZ((uint32_t)(r0 * 128) + oa2);
                uint32_t b11 = SWZ((uint32_t)(r1 * 128) + oa2);
                Ah[mi][0] = *(const uint32_t*)(sm + b00);
                Ah[mi][1] = *(const uint32_t*)(sm + b10);
                Ah[mi][2] = *(const uint32_t*)(sm + b01);
                Ah[mi][3] = *(const uint32_t*)(sm + b11);
                Al[mi][0] = *(const uint32_t*)(sm + b00 + 8);
                Al[mi][1] = *(const uint32_t*)(sm + b10 + 8);
                Al[mi][2] = *(const uint32_t*)(sm + b01 + 8);
                Al[mi][3] = *(const uint32_t*)(sm + b11 + 8);
            }
#pragma unroll
            for (int ni = 0; ni < 8; ++ni) {
                int nr = wn + ni * 8 + g;
                uint32_t ob0 = (uint32_t)(2 * s) * 32u + ((tk >> 1) * 16u) + ((tk & 1) * 4u);
                uint32_t bb0 = SWZ((uint32_t)(nr * 128) + ob0);
                uint32_t bb1 = SWZ((uint32_t)(nr * 128) + ob0 + 32u);
                uint32_t bh0 = *(const uint32_t*)(sm + 16384 + bb0);
                uint32_t bh1 = *(const uint32_t*)(sm + 16384 + bb1);
                uint32_t bl0 = *(const uint32_t*)(sm + 16384 + bb0 + 8);
                uint32_t bl1 = *(const uint32_t*)(sm + 16384 + bb1 + 8);
#pragma unroll
                for (int mi = 0; mi < 4; ++mi) {
                    mma16816(acc[mi][ni], Ah[mi][0], Ah[mi][1], Ah[mi][2], Ah[mi][3], bh0, bh1);
                    mma16816(acc[mi][ni], Al[mi][0], Al[mi][1], Al[mi][2], Al[mi][3], bh0, bh1);
                    mma16816(acc[mi][ni], Ah[mi][0], Ah[mi][1], Ah[mi][2], Ah[mi][3], bl0, bl1);
                }
            }
        }
    }

    // Epilogue
#pragma unroll
    for (int mi = 0; mi < 4; ++mi) {
#pragma unroll
        for (int ni = 0; ni < 8; ++ni) {
            int r = m0 + wm + mi * 16 + g;        // rows r and r+8
            int c = n0 + wn + ni * 8 + 2 * tk;    // cols c, c+1
            if (mode == 0) {
                int which = c >> 8;
                int h = (c >> 5) & 7;
                int d = c & 31;
                float b0, b1;
                if (which == 0)      { b0 = q_bias[c];       b1 = q_bias[c + 1]; }
                else if (which == 2) { b0 = v_bias[c - 512]; b1 = v_bias[c - 511]; }
                else                 { b0 = 0.f; b1 = 0.f; }
                float* baseP = (which == 0) ? g_Q : (which == 1) ? g_K : g_V;
                int bw0 = r >> 6, n_0 = r & 63;
                int bw1 = (r + 8) >> 6, n_1 = (r + 8) & 63;
                float2 v0 = make_float2(acc[mi][ni][0] + b0, acc[mi][ni][1] + b1);
                float2 v1 = make_float2(acc[mi][ni][2] + b0, acc[mi][ni][3] + b1);
                *(float2*)(baseP + (size_t)((bw0 * 8 + h) * 64 + n_0) * 32 + d) = v0;
                *(float2*)(baseP + (size_t)((bw1 * 8 + h) * 64 + n_1) * 32 + d) = v1;
            } else {
                float b0 = pb[c], b1 = pb[c + 1];
                float2 v0 = make_float2(acc[mi][ni][0] + b0, acc[mi][ni][1] + b1);
                float2 v1 = make_float2(acc[mi][ni][2] + b0, acc[mi][ni][3] + b1);
                *(float2*)(out + (size_t)r * 256 + c) = v0;
                *(float2*)(out + (size_t)(r + 8) * 256 + c) = v1;
            }
        }
    }
}

// ---------------------------------------------------------------------------
// Kernel 4: fused attention per window (proven R3 version, 519us)
// ---------------------------------------------------------------------------
__global__ __launch_bounds__(256) void attn_kernel(
    const float* __restrict__ mask, const float* __restrict__ logit_scale)
{
    __shared__ float qs[64][33];
    __shared__ float ks[64][33];
    __shared__ float vs[64][33];
    __shared__ float at[64][65];

    int b = blockIdx.x;
    int tid = threadIdx.x;
    int lane = tid & 31, warp = tid >> 5;
    int w_idx = b & (NW - 1);

    for (int h = 0; h < HEADS; ++h) {
        float sc = expf(fminf(logit_scale[h], 4.6051701859880913f)); // log(100)
        const float* Qg = g_Q + (size_t)(b * 8 + h) * 2048;
        const float* Kg = g_K + (size_t)(b * 8 + h) * 2048;
        const float* Vg = g_V + (size_t)(b * 8 + h) * 2048;
#pragma unroll
        for (int i = tid; i < 2048; i += 256) {
            int r = i >> 5, d = i & 31;
            qs[r][d] = Qg[i];
            ks[r][d] = Kg[i];
            vs[r][d] = Vg[i];
        }
        __syncthreads();

        for (int r = warp; r < 128; r += 8) {
            float* row = (r < 64) ? qs[r] : ks[r - 64];
            float vv = row[lane];
            float ss = vv * vv;
#pragma unroll
            for (int off = 16; off; off >>= 1)
                ss += __shfl_xor_sync(0xffffffffu, ss, off);
            float inv = 1.f / fmaxf(sqrtf(ss), 1e-12f);
            row[lane] = vv * inv;
        }
        __syncthreads();

        int ig = tid >> 4;
        int jg = tid & 15;
        float acc[4][4];
#pragma unroll
        for (int ii = 0; ii < 4; ++ii)
#pragma unroll
            for (int jj = 0; jj < 4; ++jj) acc[ii][jj] = 0.f;

#pragma unroll
        for (int d = 0; d < 32; ++d) {
            float a0 = qs[ig * 4 + 0][d];
            float a1 = qs[ig * 4 + 1][d];
            float a2 = qs[ig * 4 + 2][d];
            float a3 = qs[ig * 4 + 3][d];
#pragma unroll
            for (int jj = 0; jj < 4; ++jj) {
                float kv = ks[jg + 16 * jj][d];
                acc[0][jj] = fmaf(a0, kv, acc[0][jj]);
                acc[1][jj] = fmaf(a1, kv, acc[1][jj]);
                acc[2][jj] = fmaf(a2, kv, acc[2][jj]);
                acc[3][jj] = fmaf(a3, kv, acc[3][jj]);
            }
        }
        const float* bia = g_bias + h * 4096;
        const float* msk = mask + (size_t)w_idx * 4096;
#pragma unroll
        for (int ii = 0; ii < 4; ++ii) {
            int i = ig * 4 + ii;
#pragma unroll
            for (int jj = 0; jj < 4; ++jj) {
                int j = jg + 16 * jj;
                at[i][j] = fmaf(sc, acc[ii][jj], bia[i * 64 + j] + msk[i * 64 + j]);
            }
        }
        __syncthreads();

        for (int r = warp; r < 64; r += 8) {
            float x0 = at[r][lane], x1 = at[r][lane + 32];
            float mx = fmaxf(x0, x1);
#pragma unroll
            for (int off = 16; off; off >>= 1)
                mx = fmaxf(mx, __shfl_xor_sync(0xffffffffu, mx, off));
            float e0 = expf(x0 - mx), e1 = expf(x1 - mx);
            float s = e0 + e1;
#pragma unroll
            for (int off = 16; off; off >>= 1)
                s += __shfl_xor_sync(0xffffffffu, s, off);
            float inv = 1.f / s;
            at[r][lane] = e0 * inv;
            at[r][lane + 32] = e1 * inv;
        }
        __syncthreads();

        float o[8];
#pragma unroll
        for (int ii = 0; ii < 8; ++ii) o[ii] = 0.f;
#pragma unroll 4
        for (int j = 0; j < 64; ++j) {
            float vj = vs[j][lane];
#pragma unroll
            for (int ii = 0; ii < 8; ++ii)
                o[ii] = fmaf(at[warp * 8 + ii][j], vj, o[ii]);
        }
        float* Og = g_O + (size_t)b * 64 * 256 + h * 32;
#pragma unroll
        for (int ii = 0; ii < 8; ++ii)
            Og[(size_t)(warp * 8 + ii) * 256 + lane] = o[ii];
        __syncthreads();
    }
}

// ---------------------------------------------------------------------------
extern "C" void kernel_launch(void* const* d_in, const int* in_sizes, int n_in,
                              void* d_out, int out_size)
{
    const float* x           = (const float*)d_in[0];
    const float* mask        = (const float*)d_in[1];
    const float* qkv_w       = (const float*)d_in[2];
    const float* q_bias      = (const float*)d_in[3];
    const float* v_bias      = (const float*)d_in[4];
    const float* logit_scale = (const float*)d_in[5];
    const float* cpb_w1      = (const float*)d_in[6];
    const float* cpb_b1      = (const float*)d_in[7];
    const float* cpb_w2      = (const float*)d_in[8];
    const float* proj_w      = (const float*)d_in[9];
    const float* proj_b      = (const float*)d_in[10];
    const float* coords      = (const float*)d_in[11];
    const int*   rel_idx     = (const int*)d_in[12];
    float* out = (float*)d_out;

    static int configured = 0;
    if (!configured) {
        cudaFuncSetAttribute(mma_gemm, cudaFuncAttributeMaxDynamicSharedMemorySize,
                             GSMEM_TOTAL);
        configured = 1;
    }

    cpb_table_kernel<<<TBL, 128>>>(cpb_w1, cpb_b1, cpb_w2, coords);
    bias_gather_kernel<<<(HEADS * SEQ * SEQ + 255) / 256, 256>>>(rel_idx);
    mma_gemm<<<dim3(6, 1024), 128, GSMEM_TOTAL>>>(x, qkv_w, q_bias, v_bias,
                                                  nullptr, nullptr, 0);
    attn_kernel<<<BWIN, 256>>>(mask, logit_scale);
    mma_gemm<<<dim3(2, 1024), 128, GSMEM_TOTAL>>>(nullptr, proj_w, nullptr, nullptr,
                                                  proj_b, out, 1);
}

// round 12
// speedup vs baseline: 1.6104x; 1.0251x over previous
#include <cuda_runtime.h>
#include <cuda_bf16.h>
#include <cstdint>
#include <math.h>

// Problem constants
#define BWIN   2048
#define SEQ    64
#define DIM    256
#define HEADS  8
#define HD     32
#define NW     64
#define KDIM   256
#define TBL    225
#define CPBH   512

// Scratch (device globals)
__device__ float g_Q[BWIN * HEADS * SEQ * HD];
__device__ float g_K[BWIN * HEADS * SEQ * HD];
__device__ float g_V[BWIN * HEADS * SEQ * HD];
__device__ float g_O[BWIN * SEQ * DIM];
__device__ float g_table[TBL * HEADS];
__device__ float g_bias[HEADS * SEQ * SEQ];
__device__ float g_bm[NW * HEADS * SEQ * SEQ];   // fused bias+mask

// SW128 swizzle on byte offsets (128B rows)
#define SWZ(b) ((b) ^ (((b) >> 3) & 0x70))

// bf16 2-level split of two floats, packed as k-pair words (f0 in low half)
__device__ __forceinline__ void split2_bf(float f0, float f1,
                                          uint32_t& hi, uint32_t& lo)
{
    __nv_bfloat16 h0 = __float2bfloat16_rn(f0);
    __nv_bfloat16 h1 = __float2bfloat16_rn(f1);
    float r0 = f0 - __bfloat162float(h0);
    float r1 = f1 - __bfloat162float(h1);
    __nv_bfloat16 l0 = __float2bfloat16_rn(r0);
    __nv_bfloat16 l1 = __float2bfloat16_rn(r1);
    hi = (uint32_t)__bfloat16_as_ushort(h0) | ((uint32_t)__bfloat16_as_ushort(h1) << 16);
    lo = (uint32_t)__bfloat16_as_ushort(l0) | ((uint32_t)__bfloat16_as_ushort(l1) << 16);
}

__device__ __forceinline__ void mma16816(float* c,
    uint32_t a0, uint32_t a1, uint32_t a2, uint32_t a3,
    uint32_t b0, uint32_t b1)
{
    asm volatile(
        "mma.sync.aligned.m16n8k16.row.col.f32.bf16.bf16.f32 "
        "{%0,%1,%2,%3},{%4,%5,%6,%7},{%8,%9},{%0,%1,%2,%3};"
        : "+f"(c[0]), "+f"(c[1]), "+f"(c[2]), "+f"(c[3])
        : "r"(a0), "r"(a1), "r"(a2), "r"(a3), "r"(b0), "r"(b1));
}

// ---------------------------------------------------------------------------
// Kernel 1: CPB MLP
// ---------------------------------------------------------------------------
__global__ __launch_bounds__(128) void cpb_table_kernel(
    const float* __restrict__ w1, const float* __restrict__ b1,
    const float* __restrict__ w2, const float* __restrict__ coords)
{
    int p = blockIdx.x;
    float c0 = coords[2 * p + 0];
    float c1 = coords[2 * p + 1];
    float acc[HEADS];
#pragma unroll
    for (int h = 0; h < HEADS; ++h) acc[h] = 0.f;

    for (int j = threadIdx.x; j < CPBH; j += 128) {
        float hid = fmaf(w1[2 * j], c0, fmaf(w1[2 * j + 1], c1, b1[j]));
        hid = fmaxf(hid, 0.f);
#pragma unroll
        for (int h = 0; h < HEADS; ++h)
            acc[h] = fmaf(hid, w2[h * CPBH + j], acc[h]);
    }
    int lane = threadIdx.x & 31, warp = threadIdx.x >> 5;
#pragma unroll
    for (int h = 0; h < HEADS; ++h)
#pragma unroll
        for (int off = 16; off; off >>= 1)
            acc[h] += __shfl_xor_sync(0xffffffffu, acc[h], off);

    __shared__ float red[4][HEADS];
    if (lane == 0)
#pragma unroll
        for (int h = 0; h < HEADS; ++h) red[warp][h] = acc[h];
    __syncthreads();
    if (threadIdx.x < HEADS) {
        float s = red[0][threadIdx.x] + red[1][threadIdx.x] +
                  red[2][threadIdx.x] + red[3][threadIdx.x];
        g_table[p * HEADS + threadIdx.x] = s;
    }
}

// ---------------------------------------------------------------------------
// Kernel 2: bias gather + 16*sigmoid
// ---------------------------------------------------------------------------
__global__ __launch_bounds__(256) void bias_gather_kernel(const int* __restrict__ rel_idx)
{
    int i = blockIdx.x * 256 + threadIdx.x;
    if (i >= HEADS * SEQ * SEQ) return;
    int h = i >> 12;
    int ij = i & 4095;
    float t = g_table[rel_idx[ij] * HEADS + h];
    g_bias[i] = 16.f / (1.f + expf(-t));
}

// ---------------------------------------------------------------------------
// Kernel 2b: fuse bias[h] + mask[w] -> g_bm[w][h][ij]
// ---------------------------------------------------------------------------
__global__ __launch_bounds__(256) void bm_fuse_kernel(const float* __restrict__ mask)
{
    int i = blockIdx.x * 256 + threadIdx.x;
    if (i >= NW * HEADS * SEQ * SEQ) return;
    int wh = i >> 12;
    int ij = i & 4095;
    int w = wh >> 3, h = wh & 7;
    g_bm[i] = g_bias[h * 4096 + ij] + mask[w * 4096 + ij];
}

// ---------------------------------------------------------------------------
// 3-term bf16 mma.sync GEMM (R11-proven, unchanged)
// ---------------------------------------------------------------------------
#define GSMEM_TOTAL 32768

__global__ __launch_bounds__(128, 2) void mma_gemm(
    const float* __restrict__ A_in, const float* __restrict__ B,
    const float* __restrict__ q_bias, const float* __restrict__ v_bias,
    const float* __restrict__ pb, float* __restrict__ out, int mode)
{
    extern __shared__ char sm[];
    const float* A = (mode == 0) ? A_in : g_O;
    int tid = threadIdx.x;
    int lane = tid & 31, warp = tid >> 5;
    int m0 = blockIdx.y * 128;
    int n0 = blockIdx.x * 128;
    int wm = (warp >> 1) * 64;
    int wn = (warp & 1) * 64;

    float acc[4][8][4];
#pragma unroll
    for (int mi = 0; mi < 4; ++mi)
#pragma unroll
        for (int ni = 0; ni < 8; ++ni)
#pragma unroll
            for (int q = 0; q < 4; ++q) acc[mi][ni][q] = 0.f;

    int lrow = tid >> 2;
    int lc4 = tid & 3;
    int g = lane >> 2;
    int tk = lane & 3;

    for (int ko = 0; ko < KDIM; ko += 32) {
        __syncthreads();
#pragma unroll
        for (int q = 0; q < 4; ++q) {
            int r = lrow + q * 32;
            uint32_t base = (uint32_t)(r * 128 + lc4 * 32);
            uint32_t so  = SWZ(base);
            uint32_t so2 = SWZ(base + 16u);
            const float4* pa = (const float4*)(A + (size_t)(m0 + r) * KDIM + ko + lc4 * 8);
            float4 v0 = pa[0], v1 = pa[1];
            uint4 hi, lo;
            split2_bf(v0.x, v0.y, hi.x, lo.x);
            split2_bf(v0.z, v0.w, hi.y, lo.y);
            split2_bf(v1.x, v1.y, hi.z, lo.z);
            split2_bf(v1.z, v1.w, hi.w, lo.w);
            *(uint4*)(sm + so)  = make_uint4(hi.x, hi.y, lo.x, lo.y);
            *(uint4*)(sm + so2) = make_uint4(hi.z, hi.w, lo.z, lo.w);
            const float4* pbp = (const float4*)(B + (size_t)(n0 + r) * KDIM + ko + lc4 * 8);
            float4 w0 = pbp[0], w1 = pbp[1];
            uint4 bhi, blo;
            split2_bf(w0.x, w0.y, bhi.x, blo.x);
            split2_bf(w0.z, w0.w, bhi.y, blo.y);
            split2_bf(w1.x, w1.y, bhi.z, blo.z);
            split2_bf(w1.z, w1.w, bhi.w, blo.w);
            *(uint4*)(sm + 16384 + so)  = make_uint4(bhi.x, bhi.y, blo.x, blo.y);
            *(uint4*)(sm + 16384 + so2) = make_uint4(bhi.z, bhi.w, blo.z, blo.w);
        }
        __syncthreads();

#pragma unroll
        for (int s = 0; s < 2; ++s) {
            uint32_t Ah[4][4], Al[4][4];
#pragma unroll
            for (int mi = 0; mi < 4; ++mi) {
                int r0 = wm + mi * 16 + g;
                int r1 = r0 + 8;
                uint32_t oa0 = (uint32_t)(2 * s) * 32u + ((tk >> 1) * 16u) + ((tk & 1) * 4u);
                uint32_t oa2 = oa0 + 32u;
                uint32_t b00 = SWZ((uint32_t)(r0 * 128) + oa0);
                uint32_t b10 = SWZ((uint32_t)(r1 * 128) + oa0);
                uint32_t b01 = SWZ((uint32_t)(r0 * 128) + oa2);
                uint32_t b11 = SWZ((uint32_t)(r1 * 128) + oa2);
                Ah[mi][0] = *(const uint32_t*)(sm + b00);
                Ah[mi][1] = *(const uint32_t*)(sm + b10);
                Ah[mi][2] = *(const uint32_t*)(sm + b01);
                Ah[mi][3] = *(const uint32_t*)(sm + b11);
                Al[mi][0] = *(const uint32_t*)(sm + b00 + 8);
                Al[mi][1] = *(const uint32_t*)(sm + b10 + 8);
                Al[mi][2] = *(const uint32_t*)(sm + b01 + 8);
                Al[mi][3] = *(const uint32_t*)(sm + b11 + 8);
            }
#pragma unroll
            for (int ni = 0; ni < 8; ++ni) {
                int nr = wn + ni * 8 + g;
                uint32_t ob0 = (uint32_t)(2 * s) * 32u + ((tk >> 1) * 16u) + ((tk & 1) * 4u);
                uint32_t bb0 = SWZ((uint32_t)(nr * 128) + ob0);
                uint32_t bb1 = SWZ((uint32_t)(nr * 128) + ob0 + 32u);
                uint32_t bh0 = *(const uint32_t*)(sm + 16384 + bb0);
                uint32_t bh1 = *(const uint32_t*)(sm + 16384 + bb1);
                uint32_t bl0 = *(const uint32_t*)(sm + 16384 + bb0 + 8);
                uint32_t bl1 = *(const uint32_t*)(sm + 16384 + bb1 + 8);
#pragma unroll
                for (int mi = 0; mi < 4; ++mi) {
                    mma16816(acc[mi][ni], Ah[mi][0], Ah[mi][1], Ah[mi][2], Ah[mi][3], bh0, bh1);
                    mma16816(acc[mi][ni], Al[mi][0], Al[mi][1], Al[mi][2], Al[mi][3], bh0, bh1);
                    mma16816(acc[mi][ni], Ah[mi][0], Ah[mi][1], Ah[mi][2], Ah[mi][3], bl0, bl1);
                }
            }
        }
    }

#pragma unroll
    for (int mi = 0; mi < 4; ++mi) {
#pragma unroll
        for (int ni = 0; ni < 8; ++ni) {
            int r = m0 + wm + mi * 16 + g;
            int c = n0 + wn + ni * 8 + 2 * tk;
            if (mode == 0) {
                int which = c >> 8;
                int h = (c >> 5) & 7;
                int d = c & 31;
                float b0, b1;
                if (which == 0)      { b0 = q_bias[c];       b1 = q_bias[c + 1]; }
                else if (which == 2) { b0 = v_bias[c - 512]; b1 = v_bias[c - 511]; }
                else                 { b0 = 0.f; b1 = 0.f; }
                float* baseP = (which == 0) ? g_Q : (which == 1) ? g_K : g_V;
                int bw0 = r >> 6, n_0 = r & 63;
                int bw1 = (r + 8) >> 6, n_1 = (r + 8) & 63;
                float2 v0 = make_float2(acc[mi][ni][0] + b0, acc[mi][ni][1] + b1);
                float2 v1 = make_float2(acc[mi][ni][2] + b0, acc[mi][ni][3] + b1);
                *(float2*)(baseP + (size_t)((bw0 * 8 + h) * 64 + n_0) * 32 + d) = v0;
                *(float2*)(baseP + (size_t)((bw1 * 8 + h) * 64 + n_1) * 32 + d) = v1;
            } else {
                float b0 = pb[c], b1 = pb[c + 1];
                float2 v0 = make_float2(acc[mi][ni][0] + b0, acc[mi][ni][1] + b1);
                float2 v1 = make_float2(acc[mi][ni][2] + b0, acc[mi][ni][3] + b1);
                *(float2*)(out + (size_t)r * 256 + c) = v0;
                *(float2*)(out + (size_t)(r + 8) * 256 + c) = v1;
            }
        }
    }
}

// ---------------------------------------------------------------------------
// bf16 mma attention. CTA = 2 heads of one window (128 thr, 4 warps).
// Grid = BWIN*4. Per head: warp-pair; each warp does 32 rows.
// smem per head (words): Qh,Ql,Kh,Kl 64x20 each (d-pairs, stride 20);
// VTh,VTl 32x36 (token-pairs, stride 36). 7424 words/head, 59392 B/CTA.
// Split done ONCE at staging; P split in registers; P never hits smem.
// ---------------------------------------------------------------------------
#define ATT_HEAD_WORDS 7424
#define ATT_SMEM_BYTES (2 * ATT_HEAD_WORDS * 4)

__global__ __launch_bounds__(128) void attn_bf16(const float* __restrict__ logit_scale)
{
    extern __shared__ uint32_t smw[];
    int tid = threadIdx.x;
    int lane = tid & 31, warp = tid >> 5;
    int b = blockIdx.x >> 2;
    int h = ((blockIdx.x & 3) << 1) + (warp >> 1);
    int hp = warp >> 1;          // head slot
    int wp = warp & 1;           // warp within pair
    int wrow = wp * 32;
    int g = lane >> 2, tk = lane & 3;

    uint32_t* Qh = smw + hp * ATT_HEAD_WORDS;
    uint32_t* Ql = Qh + 1280;
    uint32_t* Kh = Ql + 1280;
    uint32_t* Kl = Kh + 1280;
    uint32_t* VTh = Kl + 1280;
    uint32_t* VTl = VTh + 1152;

    const float* Qg = g_Q + (size_t)(b * 8 + h) * 2048;
    const float* Kg = g_K + (size_t)(b * 8 + h) * 2048;
    const float* Vg = g_V + (size_t)(b * 8 + h) * 2048;

    // ---- stage Q,K: LDG -> L2-normalize (16-lane reduce) -> split -> STS ----
    {
        int half = lane >> 4;    // 0/1 : which of two consecutive rows
        int t = lane & 15;       // d-pair index
#pragma unroll
        for (int rr = 0; rr < 16; ++rr) {
            int r = wrow + rr * 2 + half;
            float2 qv = *(const float2*)(Qg + r * 32 + 2 * t);
            float ss = qv.x * qv.x + qv.y * qv.y;
            ss += __shfl_xor_sync(0xffffffffu, ss, 8, 16);
            ss += __shfl_xor_sync(0xffffffffu, ss, 4, 16);
            ss += __shfl_xor_sync(0xffffffffu, ss, 2, 16);
            ss += __shfl_xor_sync(0xffffffffu, ss, 1, 16);
            float inv = 1.f / fmaxf(sqrtf(ss), 1e-12f);
            uint32_t hw, lw;
            split2_bf(qv.x * inv, qv.y * inv, hw, lw);
            Qh[r * 20 + t] = hw;
            Ql[r * 20 + t] = lw;

            float2 kv = *(const float2*)(Kg + r * 32 + 2 * t);
            ss = kv.x * kv.x + kv.y * kv.y;
            ss += __shfl_xor_sync(0xffffffffu, ss, 8, 16);
            ss += __shfl_xor_sync(0xffffffffu, ss, 4, 16);
            ss += __shfl_xor_sync(0xffffffffu, ss, 2, 16);
            ss += __shfl_xor_sync(0xffffffffu, ss, 1, 16);
            inv = 1.f / fmaxf(sqrtf(ss), 1e-12f);
            split2_bf(kv.x * inv, kv.y * inv, hw, lw);
            Kh[r * 20 + t] = hw;
            Kl[r * 20 + t] = lw;
        }
        // V: transpose + split. word (d=lane, token-pair jp)
#pragma unroll
        for (int i = 0; i < 16; ++i) {
            int jp = wp * 16 + i;
            float v0 = Vg[(2 * jp) * 32 + lane];
            float v1 = Vg[(2 * jp + 1) * 32 + lane];
            uint32_t hw, lw;
            split2_bf(v0, v1, hw, lw);
            VTh[lane * 36 + jp] = hw;
            VTl[lane * 36 + jp] = lw;
        }
    }
    __syncthreads();

    float sc = __expf(fminf(logit_scale[h], 4.6051701859880913f));

    // ---- QK^T: rows wrow..+31 x cols 0..63, k over d=32 (2 k16-steps) ----
    float acc[2][8][4];
#pragma unroll
    for (int mi = 0; mi < 2; ++mi)
#pragma unroll
        for (int ni = 0; ni < 8; ++ni)
#pragma unroll
            for (int q = 0; q < 4; ++q) acc[mi][ni][q] = 0.f;

#pragma unroll
    for (int s = 0; s < 2; ++s) {
        int kp0 = 8 * s + tk, kp1 = kp0 + 4;
        uint32_t Ah[2][4], Al[2][4];
#pragma unroll
        for (int mi = 0; mi < 2; ++mi) {
            int r0 = wrow + mi * 16 + g;
            int r1 = r0 + 8;
            Ah[mi][0] = Qh[r0 * 20 + kp0];
            Ah[mi][1] = Qh[r1 * 20 + kp0];
            Ah[mi][2] = Qh[r0 * 20 + kp1];
            Ah[mi][3] = Qh[r1 * 20 + kp1];
            Al[mi][0] = Ql[r0 * 20 + kp0];
            Al[mi][1] = Ql[r1 * 20 + kp0];
            Al[mi][2] = Ql[r0 * 20 + kp1];
            Al[mi][3] = Ql[r1 * 20 + kp1];
        }
#pragma unroll
        for (int ni = 0; ni < 8; ++ni) {
            int n = ni * 8 + g;
            uint32_t bh0 = Kh[n * 20 + kp0];
            uint32_t bh1 = Kh[n * 20 + kp1];
            uint32_t bl0 = Kl[n * 20 + kp0];
            uint32_t bl1 = Kl[n * 20 + kp1];
#pragma unroll
            for (int mi = 0; mi < 2; ++mi) {
                mma16816(acc[mi][ni], Ah[mi][0], Ah[mi][1], Ah[mi][2], Ah[mi][3], bh0, bh1);
                mma16816(acc[mi][ni], Al[mi][0], Al[mi][1], Al[mi][2], Al[mi][3], bh0, bh1);
                mma16816(acc[mi][ni], Ah[mi][0], Ah[mi][1], Ah[mi][2], Ah[mi][3], bl0, bl1);
            }
        }
    }

    // ---- logits + softmax (registers + quad shuffles) ----
    const float* bm = g_bm + (size_t)(((b & (NW - 1)) * 8 + h)) * 4096;
#pragma unroll
    for (int mi = 0; mi < 2; ++mi) {
        int rA = wrow + mi * 16 + g;
        int rB = rA + 8;
        float mxA = -1e30f, mxB = -1e30f;
#pragma unroll
        for (int ni = 0; ni < 8; ++ni) {
            int c = ni * 8 + 2 * tk;
            float2 bA = *(const float2*)(bm + rA * 64 + c);
            float2 bB = *(const float2*)(bm + rB * 64 + c);
            acc[mi][ni][0] = fmaf(sc, acc[mi][ni][0], bA.x);
            acc[mi][ni][1] = fmaf(sc, acc[mi][ni][1], bA.y);
            acc[mi][ni][2] = fmaf(sc, acc[mi][ni][2], bB.x);
            acc[mi][ni][3] = fmaf(sc, acc[mi][ni][3], bB.y);
            mxA = fmaxf(mxA, fmaxf(acc[mi][ni][0], acc[mi][ni][1]));
            mxB = fmaxf(mxB, fmaxf(acc[mi][ni][2], acc[mi][ni][3]));
        }
        mxA = fmaxf(mxA, __shfl_xor_sync(0xffffffffu, mxA, 1));
        mxA = fmaxf(mxA, __shfl_xor_sync(0xffffffffu, mxA, 2));
        mxB = fmaxf(mxB, __shfl_xor_sync(0xffffffffu, mxB, 1));
        mxB = fmaxf(mxB, __shfl_xor_sync(0xffffffffu, mxB, 2));
        float sA = 0.f, sB = 0.f;
#pragma unroll
        for (int ni = 0; ni < 8; ++ni) {
            acc[mi][ni][0] = __expf(acc[mi][ni][0] - mxA);
            acc[mi][ni][1] = __expf(acc[mi][ni][1] - mxA);
            acc[mi][ni][2] = __expf(acc[mi][ni][2] - mxB);
            acc[mi][ni][3] = __expf(acc[mi][ni][3] - mxB);
            sA += acc[mi][ni][0] + acc[mi][ni][1];
            sB += acc[mi][ni][2] + acc[mi][ni][3];
        }
        sA += __shfl_xor_sync(0xffffffffu, sA, 1);
        sA += __shfl_xor_sync(0xffffffffu, sA, 2);
        sB += __shfl_xor_sync(0xffffffffu, sB, 1);
        sB += __shfl_xor_sync(0xffffffffu, sB, 2);
        float iA = 1.f / sA, iB = 1.f / sB;
#pragma unroll
        for (int ni = 0; ni < 8; ++ni) {
            acc[mi][ni][0] *= iA;
            acc[mi][ni][1] *= iA;
            acc[mi][ni][2] *= iB;
            acc[mi][ni][3] *= iB;
        }
    }

    // ---- AV: P from registers (split on pack), V from VT smem ----
    float o[2][4][4];
#pragma unroll
    for (int mi = 0; mi < 2; ++mi)
#pragma unroll
        for (int ni = 0; ni < 4; ++ni)
#pragma unroll
            for (int q = 0; q < 4; ++q) o[mi][ni][q] = 0.f;

#pragma unroll
    for (int s = 0; s < 4; ++s) {       // tokens 16s..16s+15
        int kp0 = 8 * s + tk, kp1 = kp0 + 4;
        uint32_t vh0[4], vh1[4], vl0[4], vl1[4];
#pragma unroll
        for (int ni = 0; ni < 4; ++ni) {
            int n = ni * 8 + g;
            vh0[ni] = VTh[n * 36 + kp0];
            vh1[ni] = VTh[n * 36 + kp1];
            vl0[ni] = VTl[n * 36 + kp0];
            vl1[ni] = VTl[n * 36 + kp1];
        }
#pragma unroll
        for (int mi = 0; mi < 2; ++mi) {
            uint32_t pah[4], pal[4];
            split2_bf(acc[mi][2 * s][0],     acc[mi][2 * s][1],     pah[0], pal[0]);
            split2_bf(acc[mi][2 * s][2],     acc[mi][2 * s][3],     pah[1], pal[1]);
            split2_bf(acc[mi][2 * s + 1][0], acc[mi][2 * s + 1][1], pah[2], pal[2]);
            split2_bf(acc[mi][2 * s + 1][2], acc[mi][2 * s + 1][3], pah[3], pal[3]);
#pragma unroll
            for (int ni = 0; ni < 4; ++ni) {
                mma16816(o[mi][ni], pah[0], pah[1], pah[2], pah[3], vh0[ni], vh1[ni]);
                mma16816(o[mi][ni], pal[0], pal[1], pal[2], pal[3], vh0[ni], vh1[ni]);
                mma16816(o[mi][ni], pah[0], pah[1], pah[2], pah[3], vl0[ni], vl1[ni]);
            }
        }
    }

    // write O
    float* Og = g_O + (size_t)b * 64 * 256 + h * 32;
#pragma unroll
    for (int mi = 0; mi < 2; ++mi) {
        int r0 = wrow + mi * 16 + g;
        int r1 = r0 + 8;
#pragma unroll
        for (int ni = 0; ni < 4; ++ni) {
            int c = ni * 8 + 2 * tk;
            *(float2*)(Og + (size_t)r0 * 256 + c) = make_float2(o[mi][ni][0], o[mi][ni][1]);
            *(float2*)(Og + (size_t)r1 * 256 + c) = make_float2(o[mi][ni][2], o[mi][ni][3]);
        }
    }
}

// ---------------------------------------------------------------------------
extern "C" void kernel_launch(void* const* d_in, const int* in_sizes, int n_in,
                              void* d_out, int out_size)
{
    const float* x           = (const float*)d_in[0];
    const float* mask        = (const float*)d_in[1];
    const float* qkv_w       = (const float*)d_in[2];
    const float* q_bias      = (const float*)d_in[3];
    const float* v_bias      = (const float*)d_in[4];
    const float* logit_scale = (const float*)d_in[5];
    const float* cpb_w1      = (const float*)d_in[6];
    const float* cpb_b1      = (const float*)d_in[7];
    const float* cpb_w2      = (const float*)d_in[8];
    const float* proj_w      = (const float*)d_in[9];
    const float* proj_b      = (const float*)d_in[10];
    const float* coords      = (const float*)d_in[11];
    const int*   rel_idx     = (const int*)d_in[12];
    float* out = (float*)d_out;

    static int configured = 0;
    if (!configured) {
        cudaFuncSetAttribute(mma_gemm, cudaFuncAttributeMaxDynamicSharedMemorySize,
                             GSMEM_TOTAL);
        cudaFuncSetAttribute(attn_bf16, cudaFuncAttributeMaxDynamicSharedMemorySize,
                             ATT_SMEM_BYTES);
        configured = 1;
    }

    cpb_table_kernel<<<TBL, 128>>>(cpb_w1, cpb_b1, cpb_w2, coords);
    bias_gather_kernel<<<(HEADS * SEQ * SEQ + 255) / 256, 256>>>(rel_idx);
    bm_fuse_kernel<<<(NW * HEADS * SEQ * SEQ + 255) / 256, 256>>>(mask);
    mma_gemm<<<dim3(6, 1024), 128, GSMEM_TOTAL>>>(x, qkv_w, q_bias, v_bias,
                                                  nullptr, nullptr, 0);
    attn_bf16<<<BWIN * 4, 128, ATT_SMEM_BYTES>>>(logit_scale);
    mma_gemm<<<dim3(2, 1024), 128, GSMEM_TOTAL>>>(nullptr, proj_w, nullptr, nullptr,
                                                  proj_b, out, 1);
}